// round 11
// baseline (speedup 1.0000x reference)
#include <cuda_runtime.h>
#include <cuda_bf16.h>
#include <math.h>

#define B_   32
#define T_   50
#define TS_  49
#define D_   100
#define NEGF (-1000000000.0f)
#define NROW (B_*TS_)   // 1568
#define NITEM (NROW*2)  // 3136

typedef unsigned long long u64;

// ---------------- device scratch ----------------
__device__ float g_e1[NROW*D_];
__device__ float g_e2[NROW*D_];
__device__ float g_et[NROW*D_];
__device__ float g_preg[NROW*400];
__device__ float g_u[NROW*D_];
__device__ float g_zq[NROW];
__device__ int   g_topk[NROW*10];
__device__ float g_vq[D_];
__device__ float g_vk[D_];
__device__ int   g_ctr;

// ---------------- fast activations ----------------
__device__ __forceinline__ float fast_sig(float x)  { return __fdividef(1.f, 1.f + __expf(-x)); }
__device__ __forceinline__ float fast_tanh(float x) { return 1.f - __fdividef(2.f, __expf(2.f*x) + 1.f); }

// ---------------- f32x2 helpers (k-pair packing) ----------------
__device__ __forceinline__ void fmx(u64& a, u64 x, u64 w) {
    asm("fma.rn.f32x2 %0, %1, %2, %0;" : "+l"(a) : "l"(x), "l"(w));
}
__device__ __forceinline__ u64 pk2(float2 v) {
    u64 r; asm("mov.b64 %0, {%1,%2};" : "=l"(r) : "f"(v.x), "f"(v.y)); return r;
}
__device__ __forceinline__ float red2(u64 a) {
    float2 f; asm("mov.b64 {%0,%1}, %2;" : "=f"(f.x), "=f"(f.y) : "l"(a));
    return f.x + f.y;
}

// =====================================================================
// k_prep
// =====================================================================
__global__ void k_prep(const float* __restrict__ Wq, const float* __restrict__ Wk,
                       const float* __restrict__ Ww)
{
    int d = threadIdx.x;
    if (d < D_) {
        float a = 0.f, c = 0.f;
        for (int e = 0; e < D_; e++) {
            a += Ww[e]       * Wq[e*D_ + d];
            c += Ww[D_ + e]  * Wk[e*D_ + d];
        }
        g_vq[d] = a; g_vk[d] = c;
    }
    if (d == 112) g_ctr = 0;
}

// =====================================================================
// k-pair mm cores. X row-major (stride 100), Wp: u64 pairs [50][ws]
// acc lanes hold (even-k, odd-k) partial sums; reduce at the end.
// =====================================================================
__device__ __forceinline__ void mmp6(const float* __restrict__ X,
                                     const u64* __restrict__ Wp, int wo,
                                     const float* __restrict__ bias,
                                     float* __restrict__ out)
{
    u64 a[24];
    #pragma unroll
    for (int i = 0; i < 24; i++) a[i] = 0;
    #pragma unroll 2
    for (int kk = 0; kk < 50; kk++) {
        ulonglong2 wA = *(const ulonglong2*)(Wp + kk*104 + wo);
        ulonglong2 wB = *(const ulonglong2*)(Wp + kk*104 + wo + 2);
        #pragma unroll
        for (int r = 0; r < 6; r++) {
            u64 xp = pk2(*(const float2*)(X + r*100 + 2*kk));
            fmx(a[r*4+0], xp, wA.x); fmx(a[r*4+1], xp, wA.y);
            fmx(a[r*4+2], xp, wB.x); fmx(a[r*4+3], xp, wB.y);
        }
    }
    float4 bb = *(const float4*)(bias + wo);
    #pragma unroll
    for (int r = 0; r < 6; r++) {
        float4 o = {fast_tanh(red2(a[r*4+0]) + bb.x), fast_tanh(red2(a[r*4+1]) + bb.y),
                    fast_tanh(red2(a[r*4+2]) + bb.z), fast_tanh(red2(a[r*4+3]) + bb.w)};
        *(float4*)(out + r*100 + wo) = o;
    }
}

__device__ __forceinline__ void mmp2(const float* __restrict__ X,
                                     const u64* __restrict__ Wp, int wo,
                                     const float* __restrict__ bias,
                                     float* __restrict__ out)
{
    u64 a[8];
    #pragma unroll
    for (int i = 0; i < 8; i++) a[i] = 0;
    #pragma unroll 2
    for (int kk = 0; kk < 50; kk++) {
        ulonglong2 wA = *(const ulonglong2*)(Wp + kk*104 + wo);
        ulonglong2 wB = *(const ulonglong2*)(Wp + kk*104 + wo + 2);
        u64 x0 = pk2(*(const float2*)(X + 2*kk));
        u64 x1 = pk2(*(const float2*)(X + 100 + 2*kk));
        fmx(a[0], x0, wA.x); fmx(a[1], x0, wA.y); fmx(a[2], x0, wB.x); fmx(a[3], x0, wB.y);
        fmx(a[4], x1, wA.x); fmx(a[5], x1, wA.y); fmx(a[6], x1, wB.x); fmx(a[7], x1, wB.y);
    }
    float4 bb = *(const float4*)(bias + wo);
    float4 o0 = {fast_tanh(red2(a[0]) + bb.x), fast_tanh(red2(a[1]) + bb.y),
                 fast_tanh(red2(a[2]) + bb.z), fast_tanh(red2(a[3]) + bb.w)};
    float4 o1 = {fast_tanh(red2(a[4]) + bb.x), fast_tanh(red2(a[5]) + bb.y),
                 fast_tanh(red2(a[6]) + bb.z), fast_tanh(red2(a[7]) + bb.w)};
    *(float4*)(out + wo)       = o0;
    *(float4*)(out + 100 + wo) = o1;
}

__device__ __forceinline__ void mmp1(const float* __restrict__ X,
                                     const u64* __restrict__ Wp, int wo,
                                     const float* __restrict__ bias,
                                     float* __restrict__ out)
{
    u64 a[4] = {0,0,0,0};
    #pragma unroll 2
    for (int kk = 0; kk < 50; kk++) {
        ulonglong2 wA = *(const ulonglong2*)(Wp + kk*104 + wo);
        ulonglong2 wB = *(const ulonglong2*)(Wp + kk*104 + wo + 2);
        u64 x0 = pk2(*(const float2*)(X + 2*kk));
        fmx(a[0], x0, wA.x); fmx(a[1], x0, wA.y); fmx(a[2], x0, wB.x); fmx(a[3], x0, wB.y);
    }
    float4 bb = *(const float4*)(bias + wo);
    float4 o = {fast_tanh(red2(a[0]) + bb.x), fast_tanh(red2(a[1]) + bb.y),
                fast_tanh(red2(a[2]) + bb.z), fast_tanh(red2(a[3]) + bb.w)};
    *(float4*)(out + wo) = o;
}

// =====================================================================
// k_agg: 512 threads = two independent halves; weights as u64 k-pairs.
// Per-half (floats): buf1[3600] buf2[3600] C[600] Dd[600] E0A[104] E0B[104] ids[272]
// =====================================================================
#define HALF_FLOATS 8880
#define AGG_SM_FLOATS (31200 + 2*HALF_FLOATS)
#define AGG_SM_BYTES  (AGG_SM_FLOATS*4)

__global__ __launch_bounds__(512, 1)
void k_agg(const int* __restrict__ question, const int* __restrict__ user,
           const int* __restrict__ mask,
           const int* __restrict__ q_nb, const int* __restrict__ s_nb,
           const int* __restrict__ u_nb, const int* __restrict__ q_nb2,
           const float* __restrict__ emb_q, const float* __restrict__ emb_q2,
           const float* __restrict__ emb_s, const float* __restrict__ emb_u,
           const float* __restrict__ agg_w, const float* __restrict__ agg_b,
           const float* __restrict__ W_al,  const float* __restrict__ b_al)
{
    extern __shared__ float sm[];
    int tid = threadIdx.x;
    int hf  = tid >> 8;
    int htid = tid & 255;

    // shared weights as k-pairs: Wp[kk*104 + c] = (W[c][2kk], W[c][2kk+1])
    u64* WP0 = (u64*)sm;              // 5200 u64
    u64* WP1 = WP0 + 5200;
    u64* WP2 = WP1 + 5200;
    for (int i = tid; i < 5200; i += 512) {
        int c = i / 50, kk = i % 50;
        int s = kk*104 + c;
        WP0[s] = pk2(*(const float2*)(agg_w + c*100 + 2*kk));
        WP1[s] = pk2(*(const float2*)(agg_w + 10000 + c*100 + 2*kk));
        WP2[s] = pk2(*(const float2*)(agg_w + 20000 + c*100 + 2*kk));
    }

    float* HB   = sm + 31200 + hf*HALF_FLOATS;
    float* buf1 = HB;           // G (raw E2) then L2 mm output
    float* buf2 = HB + 3600;    // L2 mm input (mean6(E3)+G)
    float* C    = HB + 7200;    // [6][100]
    float* Dd   = HB + 7800;    // [6][100]
    float* E0A  = HB + 8400;
    float* E0B  = HB + 8504;
    int*   ids  = (int*)(HB + 8608);
    int*   ids2 = ids + 6;
    int*   ids3 = ids + 42;
    int*   s_item = ids + 258;

    const float* b0 = agg_b;
    const float* b1 = agg_b + 100;
    const float* b2 = agg_b + 200;

    float4* G4 = (float4*)buf1; float4* D4 = (float4*)Dd; float4* E0A4 = (float4*)E0A;

    __syncthreads();

    #define HBAR() asm volatile("bar.sync %0, 256;" :: "r"(hf+1) : "memory")

    for (;;) {
        HBAR();
        if (htid == 0) *s_item = atomicAdd(&g_ctr, 1);
        HBAR();
        int item = *s_item;
        if (item >= NITEM) break;
        int side = item & 1, pair = item >> 1;
        int b = pair / TS_, t = pair % TS_;
        int m  = mask[b*T_ + t];
        int qt = question[b*T_ + t];
        float* outp = (side == 0 ? g_e1 : g_e2) + pair * D_;

        if (!m) {
            if (htid < 25) {
                const float4* src = (const float4*)((side == 0 ? emb_q : emb_q2) + (size_t)qt*D_);
                ((float4*)outp)[htid] = src[htid];
            }
            continue;
        }

        int n0; const int *tabE, *tabO; const float *embE, *embO;
        if (side == 0) { n0 = qt;           tabE = q_nb; tabO = s_nb;  embE = emb_q; embO = emb_s;  }
        else           { n0 = user[b*T_+t]; tabE = u_nb; tabO = q_nb2; embE = emb_u; embO = emb_q2; }
        const float4* embE4 = (const float4*)embE;
        const float4* embO4 = (const float4*)embO;

        // P1: ids1 + E0
        if (htid < 6) ids[htid] = tabE[n0*6 + htid];
        if (htid >= 64 && htid < 89) E0A4[htid-64] = embE4[(size_t)n0*25 + (htid-64)];
        HBAR();
        // P2: ids2
        if (htid < 36) ids2[htid] = tabO[ids[htid/6]*6 + htid%6];
        HBAR();
        // P3: ids3, buf1 <- raw E2, Dd <- E1
        if (htid < 216) ids3[htid] = tabE[ids2[htid/6]*6 + htid%6];
        for (int i = htid; i < 900; i += 256)
            G4[i] = embE4[(size_t)ids2[i/25]*25 + i%25];
        if (htid < 150)
            D4[htid] = embO4[(size_t)ids[htid/25]*25 + htid%25];
        HBAR();
        // P4: buf2 = mean6(E3)+G ; C = grpmean6(G)+Dd ; E0A += mean6(Dd)
        for (int i = htid; i < 900; i += 256) {
            int j = i/25;
            float4 a = embO4[(size_t)ids3[j*6+0]*25 + i%25];
            #pragma unroll
            for (int r = 1; r < 6; r++) {
                float4 v = embO4[(size_t)ids3[j*6+r]*25 + i%25];
                a.x += v.x; a.y += v.y; a.z += v.z; a.w += v.w;
            }
            const float s6 = 1.f/6.f;
            float4 g = G4[i];
            a.x = a.x*s6 + g.x; a.y = a.y*s6 + g.y;
            a.z = a.z*s6 + g.z; a.w = a.w*s6 + g.w;
            ((float4*)buf2)[i] = a;
        }
        for (int i = htid; i < 600; i += 256) {
            int r = i / 100, k = i % 100;
            float s = 0.f;
            #pragma unroll
            for (int j = 0; j < 6; j++) s += buf1[(r*6+j)*100 + k];
            C[i] = s * (1.f/6.f) + Dd[i];
        }
        if (htid < 100) {
            float s = 0.f;
            #pragma unroll
            for (int r = 0; r < 6; r++) s += Dd[r*100 + htid];
            E0A[htid] += s * (1.f/6.f);
        }
        HBAR();
        // P6: pass0 — one round, 250 tasks
        {
            int task = htid;
            if (task < 150) {
                int rq = task / 25, cq = task % 25;
                mmp6(buf2 + rq*6*100, WP2, cq*4, b2, buf1 + rq*6*100);
            } else if (task < 225) {
                int u = task - 150, rq = u / 25, cq = u % 25;
                mmp2(C + rq*2*100, WP1, cq*4, b1, Dd + rq*2*100);
            } else if (task < 250) {
                mmp1(E0A, WP0, (task-225)*4, b0, E0B);
            }
        }
        HBAR();
        // P7: C = grpmean6(buf1)+Dd ; E0A = mean6(Dd)+E0B
        for (int i = htid; i < 600; i += 256) {
            int r = i / 100, k = i % 100;
            float s = 0.f;
            #pragma unroll
            for (int j = 0; j < 6; j++) s += buf1[(r*6+j)*100 + k];
            C[i] = s * (1.f/6.f) + Dd[i];
        }
        if (htid < 100) {
            float s = 0.f;
            #pragma unroll
            for (int r = 0; r < 6; r++) s += Dd[r*100 + htid];
            E0A[htid] = s * (1.f/6.f) + E0B[htid];
        }
        HBAR();
        // P8: pass1 — 100 tasks
        {
            int task = htid;
            if (task < 75) {
                int rq = task / 25, cq = task % 25;
                mmp2(C + rq*2*100, WP1, cq*4, b1, Dd + rq*2*100);
            } else if (task < 100) {
                mmp1(E0A, WP0, (task-75)*4, b0, E0B);
            }
        }
        HBAR();
        // P9: E0A = mean6(Dd)+E0B
        if (htid < 100) {
            float s = 0.f;
            #pragma unroll
            for (int r = 0; r < 6; r++) s += Dd[r*100 + htid];
            E0A[htid] = s * (1.f/6.f) + E0B[htid];
        }
        HBAR();
        // P10: pass2
        if (htid < 25) mmp1(E0A, WP0, htid*4, b0, E0B);
        HBAR();
        // P11: out = tanh(WL E0B + bl), WL rows straight from L2
        if (htid < 100) {
            const float4* wl4 = (const float4*)(W_al + htid*100);
            const float4* e4  = (const float4*)E0B;
            float acc = 0.f;
            #pragma unroll 5
            for (int j = 0; j < 25; j++) {
                float4 w = __ldg(wl4 + j);
                float4 e = e4[j];
                acc += w.x*e.x + w.y*e.y + w.z*e.z + w.w*e.w;
            }
            outp[htid] = fast_tanh(acc + __ldg(b_al + htid));
        }
    }
    #undef HBAR
}

// =====================================================================
// k_att: qs rows, ql -> (u, Zq), top-10
// =====================================================================
__device__ __forceinline__ unsigned long long att_key(float f, int j)
{
    unsigned bb = __float_as_uint(f);
    bb = (bb & 0x80000000u) ? ~bb : (bb | 0x80000000u);
    return ((unsigned long long)bb << 32) | (unsigned)(49 - j);
}

__global__ void k_att(const int* __restrict__ question, const int* __restrict__ qsi,
                      const float* __restrict__ emb_q, const float* __restrict__ emb_s)
{
    __shared__ float qs[5*D_];
    __shared__ float sc[T_];
    __shared__ float qlS[5];
    __shared__ float wqS[5];
    int t = blockIdx.x, b = blockIdx.y;
    int tid = threadIdx.x, lane = tid & 31, w = tid >> 5;
    int qn = question[b*T_ + t + 1];
    const float4* embq4 = (const float4*)emb_q;
    const float4* embs4 = (const float4*)emb_s;

    for (int i = tid; i < 125; i += 256) {
        int row = i/25, dq = i%25;
        float4 v = (row == 0) ? embq4[(size_t)qn*25 + dq]
                              : embs4[(size_t)qsi[qn*4 + row - 1]*25 + dq];
        ((float4*)qs)[i] = v;
    }
    __syncthreads();
    if (w < 5) {
        float s = 0.f;
        for (int d = lane; d < D_; d += 32) s += qs[w*D_ + d] * g_vq[d];
        for (int off = 16; off; off >>= 1) s += __shfl_down_sync(0xffffffffu, s, off);
        if (lane == 0) qlS[w] = s;
    }
    for (int j = w; j < T_; j += 8) {
        int qj = question[b*T_ + j];
        float s = 0.f;
        for (int d = lane; d < D_; d += 32) s += emb_q[(size_t)qj*D_ + d] * qs[d];
        for (int off = 16; off; off >>= 1) s += __shfl_down_sync(0xffffffffu, s, off);
        if (lane == 0) sc[j] = (j < t) ? s : NEGF;
    }
    __syncthreads();
    if (w == 0) {
        bool t1 = false, t2 = false;
        int j1 = lane, j2 = lane + 32;
        for (int i = 0; i < 10; i++) {
            unsigned long long k1 = (!t1) ? att_key(sc[j1], j1) : 0ull;
            unsigned long long k2 = (j2 < T_ && !t2) ? att_key(sc[j2], j2) : 0ull;
            unsigned long long mk = k1 > k2 ? k1 : k2;
            for (int off = 16; off; off >>= 1) {
                unsigned long long o = __shfl_xor_sync(0xffffffffu, mk, off);
                if (o > mk) mk = o;
            }
            int jwin = 49 - (int)(mk & 0xffffffffull);
            if (jwin == j1) t1 = true;
            if (jwin == j2) t2 = true;
            if (lane == 0) g_topk[(b*TS_ + t)*10 + i] = (jwin < t) ? jwin : -1;
        }
    }
    __syncthreads();
    if (tid == 0) {
        float mx = qlS[0];
        for (int i = 1; i < 5; i++) mx = fmaxf(mx, qlS[i]);
        float z = 0.f;
        for (int i = 0; i < 5; i++) { wqS[i] = __expf(qlS[i] - mx); z += wqS[i]; }
        g_zq[b*TS_ + t] = z;
    }
    __syncthreads();
    if (tid < D_) {
        float u = 0.f;
        #pragma unroll
        for (int j = 0; j < 5; j++) u += wqS[j] * qs[j*D_ + tid];
        g_u[(b*TS_ + t)*D_ + tid] = u;
    }
}

// =====================================================================
// k_fuse: grid 196 = 98 rowg(16 rows) x 2 col-halves(50 cols, padded 52)
// Wp: u64 pairs [100][52]; X row-major [16][200]
// =====================================================================
#define FUSE_SM_FLOATS (10400 + 3200)
#define FUSE_SM_BYTES  (FUSE_SM_FLOATS*4)
__global__ __launch_bounds__(256, 2)
void k_fuse(const int* __restrict__ resp, const float* __restrict__ embr,
            const float* __restrict__ w1p, const float* __restrict__ w2p,
            const float* __restrict__ Wf, const float* __restrict__ bf)
{
    extern __shared__ float sm[];
    u64*   Wp = (u64*)sm;            // 5200 u64
    float* X  = sm + 10400;          // [16][200]
    int tid = threadIdx.x;
    int rowg = blockIdx.x >> 1, ch = blockIdx.x & 1;
    int g0 = rowg * 16;
    float w1 = *w1p, w2 = *w2p;

    for (int i = tid; i < 5200; i += 256) {
        int oc = i / 100, kk = i % 100;
        float2 v = (oc < 50) ? *(const float2*)(Wf + (ch*50+oc)*200 + 2*kk)
                             : make_float2(0.f, 0.f);
        Wp[kk*52 + oc] = pk2(v);
    }
    for (int i = tid; i < 3200; i += 256) {
        int r = i / 200, k = i % 200;
        int g = g0 + r, b = g / TS_, t = g % TS_;
        X[i] = (k < D_)
             ? (w1 * g_e1[g*D_ + k] + w2 * g_e2[g*D_ + k])
             : embr[resp[b*T_ + t]*D_ + (k - D_)];
    }
    __syncthreads();
    // RT2 x CT4 over 52 padded cols -> 8 rowg x 13 = 104 tasks
    for (int task = tid; task < 104; task += 256) {
        int rg = task / 13, cq = task % 13, wo = cq*4;
        const float* Xb = X + rg*2*200;
        u64 a[8];
        #pragma unroll
        for (int i = 0; i < 8; i++) a[i] = 0;
        #pragma unroll 2
        for (int kk = 0; kk < 100; kk++) {
            ulonglong2 wA = *(const ulonglong2*)(Wp + kk*52 + wo);
            ulonglong2 wB = *(const ulonglong2*)(Wp + kk*52 + wo + 2);
            u64 x0 = pk2(*(const float2*)(Xb + 2*kk));
            u64 x1 = pk2(*(const float2*)(Xb + 200 + 2*kk));
            fmx(a[0], x0, wA.x); fmx(a[1], x0, wA.y); fmx(a[2], x0, wB.x); fmx(a[3], x0, wB.y);
            fmx(a[4], x1, wA.x); fmx(a[5], x1, wA.y); fmx(a[6], x1, wB.x); fmx(a[7], x1, wB.y);
        }
        int cb = ch*50 + wo;    // global col base
        int nvalid = (wo <= 46) ? 4 : 2;   // cq==12 -> cols 48,49 only
        int r0 = g0 + rg*2;
        #pragma unroll
        for (int r = 0; r < 2; r++) {
            float o0 = fmaxf(red2(a[r*4+0]) + __ldg(bf + cb + 0), 0.f);
            float o1 = fmaxf(red2(a[r*4+1]) + __ldg(bf + cb + 1), 0.f);
            float* op = g_et + (r0+r)*D_ + cb;
            *(float2*)(op) = make_float2(o0, o1);
            if (nvalid == 4) {
                float o2 = fmaxf(red2(a[r*4+2]) + __ldg(bf + cb + 2), 0.f);
                float o3 = fmaxf(red2(a[r*4+3]) + __ldg(bf + cb + 3), 0.f);
                *(float2*)(op + 2) = make_float2(o2, o3);
            }
        }
    }
}

// =====================================================================
// k_ih: grid 196 = 98 rowg(16 rows) x 2 col-halves(200 cols)
// Wp: u64 pairs [50][204]; X row-major [16][100]
// =====================================================================
#define IH_SM_FLOATS (20400 + 1600)
#define IH_SM_BYTES  (IH_SM_FLOATS*4)
__global__ __launch_bounds__(256, 2)
void k_ih(const float* __restrict__ Wih, const float* __restrict__ bih,
          const float* __restrict__ bhh)
{
    extern __shared__ float sm[];
    u64*   Wp = (u64*)sm;            // 10200 u64
    float* X  = sm + 20400;          // [16][100]
    int tid = threadIdx.x;
    int rowg = blockIdx.x >> 1, ch = blockIdx.x & 1;
    int g0 = rowg * 16;

    for (int i = tid; i < 10000; i += 256) {
        int oc = i / 50, kk = i % 50;
        Wp[kk*204 + oc] = pk2(*(const float2*)(Wih + (ch*200+oc)*100 + 2*kk));
    }
    for (int i = tid; i < 1600; i += 256) X[i] = g_et[g0*D_ + i];
    __syncthreads();
    // RT2 x CT8 -> 8 rowg x 25 = 200 tasks
    for (int task = tid; task < 200; task += 256) {
        int rg = task / 25, cq = task % 25, wo = cq*8;
        const float* Xb = X + rg*2*100;
        u64 a[16];
        #pragma unroll
        for (int i = 0; i < 16; i++) a[i] = 0;
        #pragma unroll 2
        for (int kk = 0; kk < 50; kk++) {
            const u64* wb = Wp + kk*204 + wo;
            ulonglong2 wA = *(const ulonglong2*)(wb);
            ulonglong2 wB = *(const ulonglong2*)(wb + 2);
            ulonglong2 wC = *(const ulonglong2*)(wb + 4);
            ulonglong2 wD = *(const ulonglong2*)(wb + 6);
            u64 x0 = pk2(*(const float2*)(Xb + 2*kk));
            u64 x1 = pk2(*(const float2*)(Xb + 100 + 2*kk));
            fmx(a[0], x0, wA.x); fmx(a[1], x0, wA.y); fmx(a[2], x0, wB.x); fmx(a[3], x0, wB.y);
            fmx(a[4], x0, wC.x); fmx(a[5], x0, wC.y); fmx(a[6], x0, wD.x); fmx(a[7], x0, wD.y);
            fmx(a[8],  x1, wA.x); fmx(a[9],  x1, wA.y); fmx(a[10], x1, wB.x); fmx(a[11], x1, wB.y);
            fmx(a[12], x1, wC.x); fmx(a[13], x1, wC.y); fmx(a[14], x1, wD.x); fmx(a[15], x1, wD.y);
        }
        int cb = ch*200 + wo;
        float4 bi0 = *(const float4*)(bih + cb), bi1 = *(const float4*)(bih + cb + 4);
        float4 bh0 = *(const float4*)(bhh + cb), bh1 = *(const float4*)(bhh + cb + 4);
        int r0 = g0 + rg*2;
        #pragma unroll
        for (int r = 0; r < 2; r++) {
            const u64* ar = a + r*8;
            float4 oA = {red2(ar[0])+bi0.x+bh0.x, red2(ar[1])+bi0.y+bh0.y,
                         red2(ar[2])+bi0.z+bh0.z, red2(ar[3])+bi0.w+bh0.w};
            float4 oB = {red2(ar[4])+bi1.x+bh1.x, red2(ar[5])+bi1.y+bh1.y,
                         red2(ar[6])+bi1.z+bh1.z, red2(ar[7])+bi1.w+bh1.w};
            *(float4*)(g_preg + (r0+r)*400 + cb)     = oA;
            *(float4*)(g_preg + (r0+r)*400 + cb + 4) = oB;
        }
    }
}

// =====================================================================
// k_seq2: per-batch LSTM recurrence + in-block attention epilogue
// =====================================================================
__global__ __launch_bounds__(800, 1)
void k_seq2(const int* __restrict__ mask, const float* __restrict__ Whh,
            float* __restrict__ out)
{
    __shared__ float sh[TS_*D_];
    __shared__ float pp[800];
    __shared__ float h[104];
    __shared__ float vkS[104];
    __shared__ int maskS[T_];

    int b = blockIdx.x, tid = threadIdx.x;
    int lane = tid & 31, wid_ = tid >> 5;
    int o = tid >> 1, half = tid & 1;

    u64 w[26];
    {
        const float4* Wr = (const float4*)(Whh + o*D_ + half*52);
        #pragma unroll
        for (int j = 0; j < 13; j++) {
            if (half == 0 || j < 12) {
                float4 v = __ldg(Wr + j);
                asm("mov.b64 %0, {%1,%2};" : "=l"(w[2*j])   : "f"(v.x), "f"(v.y));
                asm("mov.b64 %0, {%1,%2};" : "=l"(w[2*j+1]) : "f"(v.z), "f"(v.w));
            } else { w[2*j] = 0; w[2*j+1] = 0; }
        }
    }
    float creg = 0.f;
    if (tid < 104) { h[tid] = 0.f; vkS[tid] = (tid < D_) ? g_vk[tid] : 0.f; }
    if (tid < T_) maskS[tid] = mask[b*T_ + tid];
    if (tid == 0) out[b*T_] = 0.5f;
    __syncthreads();

    for (int t = 0; t < TS_; t++) {
        const float* G0 = g_preg + (size_t)(b*TS_ + t) * 400;
        float gI=0.f, gF=0.f, gG=0.f, gO=0.f;
        if (tid < D_) {
            gI = __ldg(G0 + tid);        gF = __ldg(G0 + D_ + tid);
            gG = __ldg(G0 + 2*D_ + tid); gO = __ldg(G0 + 3*D_ + tid);
        }
        // partial GEMV, two independent accumulation chains
        {
            u64 acc0 = 0, acc1 = 0;
            const ulonglong2* h2 = (const ulonglong2*)(h + half*52);
            int nj = (half == 0) ? 13 : 12;
            #pragma unroll 13
            for (int j = 0; j < 13; j++) {
                if (j < nj) {
                    ulonglong2 hv = h2[j];
                    fmx(acc0, hv.x, w[2*j]);
                    fmx(acc1, hv.y, w[2*j+1]);
                }
            }
            pp[tid] = red2(acc0) + red2(acc1);
        }
        __syncthreads();
        if (tid < D_) {
            int d2 = tid*2;
            float ai = gI + pp[d2]       + pp[d2+1];
            float af = gF + pp[200 + d2] + pp[200 + d2+1];
            float ag = gG + pp[400 + d2] + pp[400 + d2+1];
            float ao = gO + pp[600 + d2] + pp[600 + d2+1];
            float c2 = fast_sig(af) * creg + fast_sig(ai) * fast_tanh(ag);
            float h2v = fast_sig(ao) * fast_tanh(c2);
            if (maskS[t]) { creg = c2; h[tid] = h2v; }
            sh[t*D_ + tid] = h[tid];
        }
        __syncthreads();
    }

    // ---- attention epilogue: t parallel across 25 warps ----
    for (int t = wid_; t < TS_; t += 25) {
        int row = b*TS_ + t;
        const float* up = g_u + (size_t)row*D_;
        float u0 = up[lane], u1 = up[32+lane], u2 = up[64+lane];
        float u3 = (lane < 4) ? up[96+lane] : 0.f;
        float kl[11], dt[11];
        #pragma unroll
        for (int j = 0; j < 11; j++) {
            int rr = (j == 0) ? t : g_topk[row*10 + j - 1];
            float s1 = 0.f, s2 = 0.f;
            if (rr >= 0) {
                const float* hp = sh + rr*D_;
                float h0 = hp[lane], h1 = hp[32+lane], h2v = hp[64+lane];
                float h3 = (lane < 4) ? hp[96+lane] : 0.f;
                s1 = h0*vkS[lane] + h1*vkS[32+lane] + h2v*vkS[64+lane]
                   + ((lane < 4) ? h3*vkS[96+lane] : 0.f);
                s2 = h0*u0 + h1*u1 + h2v*u2 + h3*u3;
            }
            for (int off = 16; off; off >>= 1) {
                s1 += __shfl_down_sync(0xffffffffu, s1, off);
                s2 += __shfl_down_sync(0xffffffffu, s2, off);
            }
            kl[j] = (rr >= 0) ? s1 : NEGF;
            dt[j] = (rr >= 0) ? s2 : 0.f;
        }
        if (lane == 0) {
            float mx = kl[0];
            #pragma unroll
            for (int j = 1; j < 11; j++) mx = fmaxf(mx, kl[j]);
            float z = 0.f, num = 0.f;
            #pragma unroll
            for (int j = 0; j < 11; j++) {
                float e = __expf(kl[j] - mx);
                z += e; num += e * dt[j];
            }
            float y = num / (g_zq[row] * z);
            out[b*T_ + t + 1] = fast_sig(y);
        }
    }
}

// =====================================================================
// launch
// =====================================================================
extern "C" void kernel_launch(void* const* d_in, const int* in_sizes, int n_in,
                              void* d_out, int out_size)
{
    const int*   user      = (const int*)  d_in[0];
    const int*   question  = (const int*)  d_in[1];
    const int*   response  = (const int*)  d_in[2];
    const int*   mask      = (const int*)  d_in[3];
    const int*   q_nb      = (const int*)  d_in[4];
    const int*   s_nb      = (const int*)  d_in[5];
    const int*   u_nb      = (const int*)  d_in[6];
    const int*   q_nb2     = (const int*)  d_in[7];
    const int*   qsi       = (const int*)  d_in[8];
    const float* emb_q     = (const float*)d_in[9];
    const float* emb_q2    = (const float*)d_in[10];
    const float* emb_s     = (const float*)d_in[11];
    const float* emb_u     = (const float*)d_in[12];
    const float* emb_r     = (const float*)d_in[13];
    const float* w1p       = (const float*)d_in[14];
    const float* w2p       = (const float*)d_in[15];
    const float* W_ih      = (const float*)d_in[16];
    const float* W_hh      = (const float*)d_in[17];
    const float* b_ih      = (const float*)d_in[18];
    const float* b_hh      = (const float*)d_in[19];
    const float* agg_w     = (const float*)d_in[20];
    const float* agg_b     = (const float*)d_in[21];
    const float* W_al      = (const float*)d_in[22];
    const float* b_al      = (const float*)d_in[23];
    const float* W_q       = (const float*)d_in[24];
    const float* W_k       = (const float*)d_in[26];
    const float* W_w       = (const float*)d_in[28];
    const float* W_f       = (const float*)d_in[30];
    const float* b_f       = (const float*)d_in[31];
    float* out = (float*)d_out;
    (void)in_sizes; (void)n_in; (void)out_size;

    cudaFuncSetAttribute(k_agg,  cudaFuncAttributeMaxDynamicSharedMemorySize, AGG_SM_BYTES);
    cudaFuncSetAttribute(k_fuse, cudaFuncAttributeMaxDynamicSharedMemorySize, FUSE_SM_BYTES);
    cudaFuncSetAttribute(k_ih,   cudaFuncAttributeMaxDynamicSharedMemorySize, IH_SM_BYTES);

    k_prep<<<1, 128>>>(W_q, W_k, W_w);
    k_att<<<dim3(TS_, B_), 256>>>(question, qsi, emb_q, emb_s);
    k_agg<<<148, 512, AGG_SM_BYTES>>>(question, user, mask,
        q_nb, s_nb, u_nb, q_nb2, emb_q, emb_q2, emb_s, emb_u,
        agg_w, agg_b, W_al, b_al);
    k_fuse<<<196, 256, FUSE_SM_BYTES>>>(response, emb_r, w1p, w2p, W_f, b_f);
    k_ih<<<196, 256, IH_SM_BYTES>>>(W_ih, b_ih, b_hh);
    k_seq2<<<B_, 800>>>(mask, W_hh, out);
}